// round 10
// baseline (speedup 1.0000x reference)
#include <cuda_runtime.h>
#include <cuda_bf16.h>

#define B_ 4
#define N_ 512
#define D_ 128
#define H_ 128

typedef unsigned long long ull;

// ---- packed f32x2 helpers -------------------------------------------------
__device__ __forceinline__ void fma2(ull &a, ull x, ull w) {
    asm("fma.rn.f32x2 %0, %1, %2, %0;" : "+l"(a) : "l"(x), "l"(w));
}
__device__ __forceinline__ ull add2(ull a, ull b) {
    ull r; asm("add.rn.f32x2 %0, %1, %2;" : "=l"(r) : "l"(a), "l"(b)); return r;
}
__device__ __forceinline__ ull pack2(float lo, float hi) {
    ull r; asm("mov.b64 %0, {%1, %2};" : "=l"(r) : "f"(lo), "f"(hi)); return r;
}
__device__ __forceinline__ void unpack2(ull v, float &lo, float &hi) {
    asm("mov.b64 {%0, %1}, %2;" : "=f"(lo), "=f"(hi) : "l"(v));
}
__device__ __forceinline__ float hadd2(ull v) { float lo, hi; unpack2(v, lo, hi); return lo + hi; }
__device__ __forceinline__ ull relu2(ull v) {
    float lo, hi; unpack2(v, lo, hi);
    return pack2(fmaxf(lo, 0.f), fmaxf(hi, 0.f));
}

// ---- scratch --------------------------------------------------------------
__device__ float gA[B_ * N_ * H_];
__device__ float gC[B_ * N_ * H_];
__device__ float gDiag[B_ * N_];

// ---------------------------------------------------------------------------
// Precompute (round-4 version, measured ~8us): 8 rows/block, 256 threads =
// h(128) x d-half(2), grid 256. Distance-2 weight prefetch (3 buffers).
// ---------------------------------------------------------------------------
#define RW 8

__global__ __launch_bounds__(256) void precompute_kernel(
    const float* __restrict__ X,
    const float* __restrict__ W1c, const float* __restrict__ b1c,
    const float* __restrict__ W1s, const float* __restrict__ b1s,
    const float* __restrict__ W2s, const float* __restrict__ b2s)
{
    const int tid  = threadIdx.x;
    const int h    = tid & 127;
    const int half = tid >> 7;
    const int rowBase = blockIdx.x * RW;

    __shared__ float xs[RW][D_];
    __shared__ float redA[RW][H_];
    __shared__ float redC[RW][H_];
    __shared__ float redS[RW][H_];
    __shared__ float red4[4][RW];

    {
        const float4* src = (const float4*)(X + (size_t)rowBase * D_);
        float4* dst = (float4*)&xs[0][0];
        for (int t = tid; t < RW * D_ / 4; t += 256) dst[t] = src[t];
    }
    __syncthreads();

    ull accA[RW], accC[RW], accS[RW];
#pragma unroll
    for (int r = 0; r < RW; r++) { accA[r] = 0ull; accC[r] = 0ull; accS[r] = 0ull; }

    const int dBase = half * 64;
    const float* pA = W1c + (size_t)dBase * H_ + h;
    const float* pC = W1c + (size_t)(dBase + D_) * H_ + h;
    const float* pS = W1s + (size_t)dBase * H_ + h;

    float wb[3][12];
#pragma unroll
    for (int p = 0; p < 2; p++) {
#pragma unroll
        for (int q = 0; q < 4; q++) {
            wb[p][q]     = pA[(p * 4 + q) * H_];
            wb[p][4 + q] = pC[(p * 4 + q) * H_];
            wb[p][8 + q] = pS[(p * 4 + q) * H_];
        }
    }

#pragma unroll
    for (int cc = 0; cc < 16; cc++) {
        const int cur = cc % 3;
        if (cc < 14) {
            const int nb  = (cc + 2) % 3;
            const int off = (cc + 2) * 4;
#pragma unroll
            for (int q = 0; q < 4; q++) {
                wb[nb][q]     = pA[(off + q) * H_];
                wb[nb][4 + q] = pC[(off + q) * H_];
                wb[nb][8 + q] = pS[(off + q) * H_];
            }
        }
        const ull wa01 = pack2(wb[cur][0], wb[cur][1]);
        const ull wa23 = pack2(wb[cur][2], wb[cur][3]);
        const ull wc01 = pack2(wb[cur][4], wb[cur][5]);
        const ull wc23 = pack2(wb[cur][6], wb[cur][7]);
        const ull ws01 = pack2(wb[cur][8], wb[cur][9]);
        const ull ws23 = pack2(wb[cur][10], wb[cur][11]);
        const int d0 = dBase + cc * 4;
#pragma unroll
        for (int r = 0; r < RW; r++) {
            const ulonglong2 xv = *(const ulonglong2*)&xs[r][d0];
            fma2(accA[r], xv.x, wa01); fma2(accA[r], xv.y, wa23);
            fma2(accC[r], xv.x, wc01); fma2(accC[r], xv.y, wc23);
            fma2(accS[r], xv.x, ws01); fma2(accS[r], xv.y, ws23);
        }
    }

    if (half == 1) {
#pragma unroll
        for (int r = 0; r < RW; r++) {
            redA[r][h] = hadd2(accA[r]);
            redC[r][h] = hadd2(accC[r]);
            redS[r][h] = hadd2(accS[r]);
        }
    }
    __syncthreads();

    if (half == 0) {
        const float bc = b1c[h];
        const float bs = b1s[h];
        const float w2 = W2s[h];
#pragma unroll
        for (int r = 0; r < RW; r++) {
            const float a = hadd2(accA[r]) + redA[r][h];
            const float c = hadd2(accC[r]) + redC[r][h] + bc;
            gA[(size_t)(rowBase + r) * H_ + h] = a;
            gC[(size_t)(rowBase + r) * H_ + h] = c;
            float t = fmaxf(hadd2(accS[r]) + redS[r][h] + bs, 0.f) * w2;
#pragma unroll
            for (int off = 16; off > 0; off >>= 1)
                t += __shfl_down_sync(0xffffffffu, t, off);
            if ((h & 31) == 0) red4[h >> 5][r] = t;
        }
    }
    __syncthreads();
    if (tid < RW) {
        const float s = red4[0][tid] + red4[1][tid] + red4[2][tid] + red4[3][tid] + b2s[0];
        gDiag[rowBase + tid] = 1.f / (1.f + __expf(-s));
    }
}

// ---------------------------------------------------------------------------
// Pair kernel v10: each 64x64 tile split into top/bottom 32x64 half-tiles.
// 288 blocks x 256 threads (8 warps), 4x2 micro: ty = warp -> A-row loads are
// warp broadcasts; tx = lane -> C loads conflict-free. ~2 blocks/SM resident.
// ---------------------------------------------------------------------------
#define PSTRIDE 132
#define SMEM_PAIR_BYTES ((32 * PSTRIDE + 64 * PSTRIDE + 128 + 32) * 4)

__global__ __launch_bounds__(256) void pair_kernel(
    const float* __restrict__ W2c, const float* __restrict__ b2c,
    float* __restrict__ out)
{
    extern __shared__ float sm[];
    float* As = sm;                           // [32][132]
    float* Cs = sm + 32 * PSTRIDE;            // [64][132]
    float* ws = sm + (32 + 64) * PSTRIDE;     // [128]

    // decode: blockIdx.x = tile*2 + half
    int t = blockIdx.x >> 1;
    const int half = blockIdx.x & 1;
    int ti = 0;
    while (t >= 8 - ti) { t -= 8 - ti; ti++; }
    const int tj = ti + t;
    const int b  = blockIdx.y;

    const int tid = threadIdx.x;
    const int i0 = ti * 64 + half * 32;   // this block's 32 rows
    const int j0 = tj * 64;               // full 64 cols
    const bool diag = (ti == tj);

    // loads (float4, coalesced): As 1024 f4 (4/thread), Cs 2048 f4 (8/thread)
    {
        const float4* ga4 = (const float4*)(gA + ((size_t)b * N_ + i0) * H_);
        const float4* gc4 = (const float4*)(gC + ((size_t)b * N_ + j0) * H_);
#pragma unroll
        for (int k = 0; k < 4; k++) {
            const int e = k * 256 + tid;            // 0..1023
            const int r = e >> 5, c = e & 31;
            ((float4*)&As[r * PSTRIDE])[c] = ga4[r * 32 + c];
        }
#pragma unroll
        for (int k = 0; k < 8; k++) {
            const int e = k * 256 + tid;            // 0..2047
            const int r = e >> 5, c = e & 31;
            ((float4*)&Cs[r * PSTRIDE])[c] = gc4[r * 32 + c];
        }
        if (tid < H_) ws[tid] = W2c[tid];
    }
    __syncthreads();

    const int ty = tid >> 5;     // warp id 0..7 -> rows ty+8k (warp-uniform)
    const int tx = tid & 31;     // lane         -> cols tx+32m

    ull acc[4][2];
#pragma unroll
    for (int k = 0; k < 4; k++) { acc[k][0] = 0ull; acc[k][1] = 0ull; }

#pragma unroll 4
    for (int hh = 0; hh < H_; hh += 4) {
        ulonglong2 av[4], cv[2];
#pragma unroll
        for (int k = 0; k < 4; k++)
            av[k] = *(const ulonglong2*)&As[(ty + 8 * k) * PSTRIDE + hh];   // broadcast
#pragma unroll
        for (int m = 0; m < 2; m++)
            cv[m] = *(const ulonglong2*)&Cs[(tx + 32 * m) * PSTRIDE + hh];
        const ulonglong2 wv = *(const ulonglong2*)&ws[hh];

#pragma unroll
        for (int k = 0; k < 4; k++) {
#pragma unroll
            for (int m = 0; m < 2; m++) {
                fma2(acc[k][m], relu2(add2(av[k].x, cv[m].x)), wv.x);
                fma2(acc[k][m], relu2(add2(av[k].y, cv[m].y)), wv.y);
            }
        }
    }

    const float bb = b2c[0];
    float sv[4][2];
#pragma unroll
    for (int k = 0; k < 4; k++)
#pragma unroll
        for (int m = 0; m < 2; m++)
            sv[k][m] = 1.f / (1.f + __expf(-(hadd2(acc[k][m]) + bb)));

    // stage results: St[32][65] aliased onto As (all As/Cs reads done)
    __syncthreads();
    float* St = As;
#define ST(i, j) St[(i) * 65 + (j)]

    if (!diag) {
#pragma unroll
        for (int k = 0; k < 4; k++)
#pragma unroll
            for (int m = 0; m < 2; m++)
                ST(ty + 8 * k, tx + 32 * m) = sv[k][m];
        __syncthreads();

        // direct: 32 rows x 64 cols = 512 f4, 2 per thread
#pragma unroll
        for (int p = 0; p < 2; p++) {
            const int q = p * 256 + tid;
            const int r = q >> 4, c = (q & 15) * 4;
            float4 v = make_float4(ST(r, c), ST(r, c + 1), ST(r, c + 2), ST(r, c + 3));
            *(float4*)&out[((size_t)b * N_ + i0 + r) * N_ + j0 + c] = v;
        }
        // transposed band: 64 rows x 32 cols = 512 f4
#pragma unroll
        for (int p = 0; p < 2; p++) {
            const int q = p * 256 + tid;
            const int R = q >> 3, C = (q & 7) * 4;
            float4 v = make_float4(ST(C, R), ST(C + 1, R), ST(C + 2, R), ST(C + 3, R));
            *(float4*)&out[((size_t)b * N_ + j0 + R) * N_ + i0 + C] = v;
        }
    } else if (half == 0) {
        // top half of a diagonal tile: tile rows [0,32), all 64 cols
        const int gd = b * N_ + i0;
#pragma unroll
        for (int k = 0; k < 4; k++) {
#pragma unroll
            for (int m = 0; m < 2; m++) {
                const int i = ty + 8 * k, j = tx + 32 * m;    // tile coords
                if (i < j)       ST(i, j) = sv[k][m];
                else if (i == j) ST(i, i) = gDiag[gd + i];
                // i > j: filled by fixup
            }
        }
        __syncthreads();
        // symmetrize left 32x32 square
        for (int q = tid; q < 32 * 32; q += 256) {
            const int r = q >> 5, c = q & 31;
            if (r > c) ST(r, c) = ST(c, r);
        }
        __syncthreads();

#pragma unroll
        for (int p = 0; p < 2; p++) {
            const int q = p * 256 + tid;
            const int r = q >> 4, c = (q & 15) * 4;
            float4 v = make_float4(ST(r, c), ST(r, c + 1), ST(r, c + 2), ST(r, c + 3));
            *(float4*)&out[((size_t)b * N_ + i0 + r) * N_ + j0 + c] = v;
        }
#pragma unroll
        for (int p = 0; p < 2; p++) {
            const int q = p * 256 + tid;
            const int R = q >> 3, C = (q & 7) * 4;
            float4 v = make_float4(ST(C, R), ST(C + 1, R), ST(C + 2, R), ST(C + 3, R));
            *(float4*)&out[((size_t)b * N_ + j0 + R) * N_ + i0 + C] = v;
        }
    } else {
        // bottom half of a diagonal tile: tile rows [32,64), only cols [32,64)
        const int gd = b * N_ + i0;   // i0 = ti*64 + 32
#pragma unroll
        for (int k = 0; k < 4; k++) {
            const int rloc = ty + 8 * k;          // 0..31, tile row = 32+rloc
            const int j = tx + 32;                // m=1 only; tile col
            if (32 + rloc < j)       ST(rloc, j) = sv[k][1];
            else if (32 + rloc == j) ST(rloc, j) = gDiag[gd + rloc];
        }
        __syncthreads();
        // symmetrize right 32x32 square: St(r, 32+c), r>c  <-  St(c, 32+r)
        for (int q = tid; q < 32 * 32; q += 256) {
            const int r = q >> 5, c = q & 31;
            if (r > c) ST(r, 32 + c) = ST(c, 32 + r);
        }
        __syncthreads();
        // write only cols [32,64): 32 rows x 32 cols = 256 f4, 1 per thread
        {
            const int r = tid >> 3, c = 32 + (tid & 7) * 4;
            float4 v = make_float4(ST(r, c), ST(r, c + 1), ST(r, c + 2), ST(r, c + 3));
            *(float4*)&out[((size_t)b * N_ + i0 + r) * N_ + j0 + c] = v;
        }
    }
#undef ST
}

// ---------------------------------------------------------------------------
extern "C" void kernel_launch(void* const* d_in, const int* in_sizes, int n_in,
                              void* d_out, int out_size)
{
    const float* X   = (const float*)d_in[0];
    const float* W1c = (const float*)d_in[1];
    const float* b1c = (const float*)d_in[2];
    const float* W2c = (const float*)d_in[3];
    const float* b2c = (const float*)d_in[4];
    const float* W1s = (const float*)d_in[5];
    const float* b1s = (const float*)d_in[6];
    const float* W2s = (const float*)d_in[7];
    const float* b2s = (const float*)d_in[8];
    float* out = (float*)d_out;

    static bool attrSet = false;
    if (!attrSet) {
        cudaFuncSetAttribute(pair_kernel,
                             cudaFuncAttributeMaxDynamicSharedMemorySize,
                             SMEM_PAIR_BYTES);
        attrSet = true;
    }

    precompute_kernel<<<(B_ * N_) / RW, 256>>>(X, W1c, b1c, W1s, b1s, W2s, b2s);

    dim3 grid(72, B_);   // 36 triangular 64x64 tiles x 2 half-tiles x batch
    pair_kernel<<<grid, 256, SMEM_PAIR_BYTES>>>(W2c, b2c, out);
}

// round 11
// speedup vs baseline: 1.0126x; 1.0126x over previous
#include <cuda_runtime.h>
#include <cuda_bf16.h>

#define B_ 4
#define N_ 512
#define D_ 128
#define H_ 128

typedef unsigned long long ull;

// ---- packed f32x2 helpers -------------------------------------------------
__device__ __forceinline__ void fma2(ull &a, ull x, ull w) {
    asm("fma.rn.f32x2 %0, %1, %2, %0;" : "+l"(a) : "l"(x), "l"(w));
}
__device__ __forceinline__ ull add2(ull a, ull b) {
    ull r; asm("add.rn.f32x2 %0, %1, %2;" : "=l"(r) : "l"(a), "l"(b)); return r;
}
__device__ __forceinline__ ull pack2(float lo, float hi) {
    ull r; asm("mov.b64 %0, {%1, %2};" : "=l"(r) : "f"(lo), "f"(hi)); return r;
}
__device__ __forceinline__ void unpack2(ull v, float &lo, float &hi) {
    asm("mov.b64 {%0, %1}, %2;" : "=f"(lo), "=f"(hi) : "l"(v));
}
__device__ __forceinline__ float hadd2(ull v) { float lo, hi; unpack2(v, lo, hi); return lo + hi; }
__device__ __forceinline__ ull relu2(ull v) {
    float lo, hi; unpack2(v, lo, hi);
    return pack2(fmaxf(lo, 0.f), fmaxf(hi, 0.f));
}

// ---- scratch --------------------------------------------------------------
__device__ float gA[B_ * N_ * H_];
__device__ float gC[B_ * N_ * H_];
__device__ float gDiagP[2][B_ * N_];   // per-h-half partial diag sums

// ---------------------------------------------------------------------------
// Precompute v11: grid (128 row-blocks, 2 h-halves). Each block: 16 rows x
// 64 h-cols, reads only 96KB of W (total 24MB L2 vs 48MB before).
// 256 threads = h64(64) x dhalf(2) x rowgroup(2, 8 rows each).
// Distance-2 W register prefetch (3 buffers), proven round-4 loop structure.
// ---------------------------------------------------------------------------
#define PR_ROWS 16

__global__ __launch_bounds__(256) void precompute_kernel(
    const float* __restrict__ X,
    const float* __restrict__ W1c, const float* __restrict__ b1c,
    const float* __restrict__ W1s, const float* __restrict__ b1s,
    const float* __restrict__ W2s)
{
    const int tid = threadIdx.x;
    const int h64 = tid & 63;
    const int sub = tid >> 6;       // 0..3
    const int dh  = sub & 1;        // d-half
    const int rg  = sub >> 1;       // row group (8 rows)
    const int rb  = blockIdx.x * PR_ROWS;
    const int hh  = blockIdx.y;     // h-half
    const int h   = hh * 64 + h64;

    __shared__ float xs[PR_ROWS][D_];      // 8 KB
    __shared__ float redA[PR_ROWS][64];    // 4 KB
    __shared__ float redC[PR_ROWS][64];    // 4 KB
    __shared__ float redS[PR_ROWS][64];    // 4 KB
    __shared__ float redD[PR_ROWS][2];

    {
        const float4* src = (const float4*)(X + (size_t)rb * D_);
        float4* dst = (float4*)&xs[0][0];
#pragma unroll
        for (int k = 0; k < 2; k++) dst[k * 256 + tid] = src[k * 256 + tid];
    }
    __syncthreads();

    ull accA[8], accC[8], accS[8];
#pragma unroll
    for (int r = 0; r < 8; r++) { accA[r] = 0ull; accC[r] = 0ull; accS[r] = 0ull; }

    const int dBase = dh * 64;
    const float* pA = W1c + (size_t)dBase * H_ + h;
    const float* pC = W1c + (size_t)(dBase + D_) * H_ + h;
    const float* pS = W1s + (size_t)dBase * H_ + h;

    float wb[3][12];
#pragma unroll
    for (int p = 0; p < 2; p++) {
#pragma unroll
        for (int q = 0; q < 4; q++) {
            wb[p][q]     = pA[(p * 4 + q) * H_];
            wb[p][4 + q] = pC[(p * 4 + q) * H_];
            wb[p][8 + q] = pS[(p * 4 + q) * H_];
        }
    }

#pragma unroll
    for (int cc = 0; cc < 16; cc++) {
        const int cur = cc % 3;
        if (cc < 14) {
            const int nb  = (cc + 2) % 3;
            const int off = (cc + 2) * 4;
#pragma unroll
            for (int q = 0; q < 4; q++) {
                wb[nb][q]     = pA[(off + q) * H_];
                wb[nb][4 + q] = pC[(off + q) * H_];
                wb[nb][8 + q] = pS[(off + q) * H_];
            }
        }
        const ull wa01 = pack2(wb[cur][0], wb[cur][1]);
        const ull wa23 = pack2(wb[cur][2], wb[cur][3]);
        const ull wc01 = pack2(wb[cur][4], wb[cur][5]);
        const ull wc23 = pack2(wb[cur][6], wb[cur][7]);
        const ull ws01 = pack2(wb[cur][8], wb[cur][9]);
        const ull ws23 = pack2(wb[cur][10], wb[cur][11]);
        const int d0 = dBase + cc * 4;
#pragma unroll
        for (int r = 0; r < 8; r++) {
            const ulonglong2 xv = *(const ulonglong2*)&xs[rg * 8 + r][d0];
            fma2(accA[r], xv.x, wa01); fma2(accA[r], xv.y, wa23);
            fma2(accC[r], xv.x, wc01); fma2(accC[r], xv.y, wc23);
            fma2(accS[r], xv.x, ws01); fma2(accS[r], xv.y, ws23);
        }
    }

    if (dh == 1) {
#pragma unroll
        for (int r = 0; r < 8; r++) {
            redA[rg * 8 + r][h64] = hadd2(accA[r]);
            redC[rg * 8 + r][h64] = hadd2(accC[r]);
            redS[rg * 8 + r][h64] = hadd2(accS[r]);
        }
    }
    __syncthreads();

    if (dh == 0) {
        const float bc = b1c[h];
        const float bs = b1s[h];
        const float w2 = W2s[h];
        const int wwi = (tid >> 5) & 1;   // which 32-h warp within this rg
#pragma unroll
        for (int r = 0; r < 8; r++) {
            const int rl = rg * 8 + r;
            const int row = rb + rl;
            const float a = hadd2(accA[r]) + redA[rl][h64];
            const float c = hadd2(accC[r]) + redC[rl][h64] + bc;
            gA[(size_t)row * H_ + h] = a;
            gC[(size_t)row * H_ + h] = c;
            float t = fmaxf(hadd2(accS[r]) + redS[rl][h64] + bs, 0.f) * w2;
#pragma unroll
            for (int off = 16; off > 0; off >>= 1)
                t += __shfl_down_sync(0xffffffffu, t, off);
            if ((tid & 31) == 0) redD[rl][wwi] = t;
        }
    }
    __syncthreads();
    if (tid < PR_ROWS)
        gDiagP[hh][rb + tid] = redD[tid][0] + redD[tid][1];
}

// ---------------------------------------------------------------------------
// Pair kernel v11: v9 (64x64 tile, 512 thr, 4x2 micro, warp-broadcast A rows)
// + explicit software-pipelined fragment loads (double register buffer).
// ---------------------------------------------------------------------------
#define PSTRIDE 132
#define SMEM_PAIR_BYTES ((2 * 64 * PSTRIDE + 128 + 32) * 4)

__global__ __launch_bounds__(512) void pair_kernel(
    const float* __restrict__ W2c, const float* __restrict__ b2c,
    const float* __restrict__ b2s, float* __restrict__ out)
{
    extern __shared__ float sm[];
    float* As = sm;                          // [64][132]
    float* Cs = sm + 64 * PSTRIDE;           // [64][132]
    float* ws = sm + 2 * 64 * PSTRIDE;       // [128]

    int t = blockIdx.x, ti = 0;
    while (t >= 8 - ti) { t -= 8 - ti; ti++; }
    const int tj = ti + t;
    const int b  = blockIdx.y;

    const int tid = threadIdx.x;
    const int i0 = ti * 64, j0 = tj * 64;

    {
        const float4* ga4 = (const float4*)(gA + ((size_t)b * N_ + i0) * H_);
        const float4* gc4 = (const float4*)(gC + ((size_t)b * N_ + j0) * H_);
#pragma unroll
        for (int k = 0; k < 4; k++) {
            const int e = k * 512 + tid;
            const int r = e >> 5, c = e & 31;
            ((float4*)&As[r * PSTRIDE])[c] = ga4[r * 32 + c];
            ((float4*)&Cs[r * PSTRIDE])[c] = gc4[r * 32 + c];
        }
        if (tid < H_) ws[tid] = W2c[tid];
    }
    __syncthreads();

    const int ty = tid >> 5;     // warp id -> rows ty+16k (broadcast loads)
    const int tx = tid & 31;     // lane    -> cols tx+32m (conflict-free)

    const float* aBase = &As[ty * PSTRIDE];
    const float* cBase = &Cs[tx * PSTRIDE];

    ull acc[4][2];
#pragma unroll
    for (int k = 0; k < 4; k++) { acc[k][0] = 0ull; acc[k][1] = 0ull; }

    // software-pipelined mainloop: fragments double-buffered in registers
    ulonglong2 avb[2][4], cvb[2][2], wvb[2];
#pragma unroll
    for (int k = 0; k < 4; k++) avb[0][k] = *(const ulonglong2*)(aBase + (16 * k) * PSTRIDE);
#pragma unroll
    for (int m = 0; m < 2; m++) cvb[0][m] = *(const ulonglong2*)(cBase + (32 * m) * PSTRIDE);
    wvb[0] = *(const ulonglong2*)&ws[0];

#pragma unroll 2
    for (int s = 0; s < 32; s++) {
        const int cur = s & 1, nxt = cur ^ 1;
        if (s < 31) {
            const int hn = (s + 1) * 4;
#pragma unroll
            for (int k = 0; k < 4; k++)
                avb[nxt][k] = *(const ulonglong2*)(aBase + (16 * k) * PSTRIDE + hn);
#pragma unroll
            for (int m = 0; m < 2; m++)
                cvb[nxt][m] = *(const ulonglong2*)(cBase + (32 * m) * PSTRIDE + hn);
            wvb[nxt] = *(const ulonglong2*)&ws[hn];
        }
#pragma unroll
        for (int k = 0; k < 4; k++) {
#pragma unroll
            for (int m = 0; m < 2; m++) {
                fma2(acc[k][m], relu2(add2(avb[cur][k].x, cvb[cur][m].x)), wvb[cur].x);
                fma2(acc[k][m], relu2(add2(avb[cur][k].y, cvb[cur][m].y)), wvb[cur].y);
            }
        }
    }

    const float bb = b2c[0];
    float sv[4][2];
#pragma unroll
    for (int k = 0; k < 4; k++)
#pragma unroll
        for (int m = 0; m < 2; m++)
            sv[k][m] = 1.f / (1.f + __expf(-(hadd2(acc[k][m]) + bb)));

    __syncthreads();
    float* St = As;
#define ST(i, j) St[(i) * 65 + (j)]

    if (ti != tj) {
#pragma unroll
        for (int k = 0; k < 4; k++)
#pragma unroll
            for (int m = 0; m < 2; m++)
                ST(ty + 16 * k, tx + 32 * m) = sv[k][m];
        __syncthreads();

        for (int q = tid; q < 1024; q += 512) {
            const int r = q >> 4, c = (q & 15) * 4;
            float4 v = make_float4(ST(r, c), ST(r, c + 1), ST(r, c + 2), ST(r, c + 3));
            *(float4*)&out[((size_t)b * N_ + i0 + r) * N_ + j0 + c] = v;
        }
        for (int q = tid; q < 1024; q += 512) {
            const int r = q >> 4, c = (q & 15) * 4;
            float4 v = make_float4(ST(c, r), ST(c + 1, r), ST(c + 2, r), ST(c + 3, r));
            *(float4*)&out[((size_t)b * N_ + j0 + r) * N_ + i0 + c] = v;
        }
    } else {
        const int gi0 = b * N_ + i0;
        const float bsv = b2s[0];
#pragma unroll
        for (int k = 0; k < 4; k++) {
#pragma unroll
            for (int m = 0; m < 2; m++) {
                const int i = ty + 16 * k, j = tx + 32 * m;
                if (i < j) { ST(i, j) = sv[k][m]; ST(j, i) = sv[k][m]; }
                else if (i == j) {
                    const float p = gDiagP[0][gi0 + i] + gDiagP[1][gi0 + i] + bsv;
                    ST(i, i) = 1.f / (1.f + __expf(-p));
                }
            }
        }
        __syncthreads();
        for (int q = tid; q < 1024; q += 512) {
            const int r = q >> 4, c = (q & 15) * 4;
            float4 v = make_float4(ST(r, c), ST(r, c + 1), ST(r, c + 2), ST(r, c + 3));
            *(float4*)&out[((size_t)b * N_ + i0 + r) * N_ + j0 + c] = v;
        }
    }
#undef ST
}

// ---------------------------------------------------------------------------
extern "C" void kernel_launch(void* const* d_in, const int* in_sizes, int n_in,
                              void* d_out, int out_size)
{
    const float* X   = (const float*)d_in[0];
    const float* W1c = (const float*)d_in[1];
    const float* b1c = (const float*)d_in[2];
    const float* W2c = (const float*)d_in[3];
    const float* b2c = (const float*)d_in[4];
    const float* W1s = (const float*)d_in[5];
    const float* b1s = (const float*)d_in[6];
    const float* W2s = (const float*)d_in[7];
    const float* b2s = (const float*)d_in[8];
    float* out = (float*)d_out;

    static bool attrSet = false;
    if (!attrSet) {
        cudaFuncSetAttribute(pair_kernel,
                             cudaFuncAttributeMaxDynamicSharedMemorySize,
                             SMEM_PAIR_BYTES);
        attrSet = true;
    }

    dim3 pgrid((B_ * N_) / PR_ROWS, 2);   // 128 row-blocks x 2 h-halves
    precompute_kernel<<<pgrid, 256>>>(X, W1c, b1c, W1s, b1s, W2s);

    dim3 grid(36, B_);   // triangular 64x64 tiles x batch
    pair_kernel<<<grid, 512, SMEM_PAIR_BYTES>>>(W2c, b2c, b2s, out);
}

// round 12
// speedup vs baseline: 1.1125x; 1.0986x over previous
#include <cuda_runtime.h>
#include <cuda_bf16.h>

#define B_ 4
#define N_ 512
#define D_ 128
#define H_ 128

typedef unsigned long long ull;
#define ABSMASK2 0x7fffffff7fffffffULL

// ---- packed f32x2 helpers -------------------------------------------------
__device__ __forceinline__ void fma2(ull &a, ull x, ull w) {
    asm("fma.rn.f32x2 %0, %1, %2, %0;" : "+l"(a) : "l"(x), "l"(w));
}
__device__ __forceinline__ ull add2(ull a, ull b) {
    ull r; asm("add.rn.f32x2 %0, %1, %2;" : "=l"(r) : "l"(a), "l"(b)); return r;
}
__device__ __forceinline__ ull pack2(float lo, float hi) {
    ull r; asm("mov.b64 %0, {%1, %2};" : "=l"(r) : "f"(lo), "f"(hi)); return r;
}
__device__ __forceinline__ void unpack2(ull v, float &lo, float &hi) {
    asm("mov.b64 {%0, %1}, %2;" : "=f"(lo), "=f"(hi) : "l"(v));
}
__device__ __forceinline__ float hadd2(ull v) { float lo, hi; unpack2(v, lo, hi); return lo + hi; }

// ---- scratch --------------------------------------------------------------
__device__ float gA[B_ * N_ * H_];
__device__ float gC[B_ * N_ * H_];
__device__ float gWA[B_ * N_];       // sum_h W2c[h]*A[row][h]
__device__ float gWC[B_ * N_];       // sum_h W2c[h]*C[row][h]
__device__ float gDiag[B_ * N_];

// ---------------------------------------------------------------------------
// Precompute (proven round-4 core): 8 rows/block, 256 threads = h(128) x
// d-half(2), grid 256. Distance-2 weight prefetch. Epilogue additionally
// produces gWA / gWC (linear parts of the relu-abs identity) and gDiag.
// ---------------------------------------------------------------------------
#define RW 8

__global__ __launch_bounds__(256) void precompute_kernel(
    const float* __restrict__ X,
    const float* __restrict__ W1c, const float* __restrict__ b1c,
    const float* __restrict__ W1s, const float* __restrict__ b1s,
    const float* __restrict__ W2s, const float* __restrict__ b2s,
    const float* __restrict__ W2c)
{
    const int tid  = threadIdx.x;
    const int h    = tid & 127;
    const int half = tid >> 7;
    const int rowBase = blockIdx.x * RW;

    __shared__ float xs[RW][D_];
    __shared__ float redA[RW][H_];
    __shared__ float redC[RW][H_];
    __shared__ float redS[RW][H_];
    __shared__ float red4d[4][RW];
    __shared__ float red4a[4][RW];
    __shared__ float red4c[4][RW];

    {
        const float4* src = (const float4*)(X + (size_t)rowBase * D_);
        float4* dst = (float4*)&xs[0][0];
        for (int t = tid; t < RW * D_ / 4; t += 256) dst[t] = src[t];
    }
    __syncthreads();

    ull accA[RW], accC[RW], accS[RW];
#pragma unroll
    for (int r = 0; r < RW; r++) { accA[r] = 0ull; accC[r] = 0ull; accS[r] = 0ull; }

    const int dBase = half * 64;
    const float* pA = W1c + (size_t)dBase * H_ + h;
    const float* pC = W1c + (size_t)(dBase + D_) * H_ + h;
    const float* pS = W1s + (size_t)dBase * H_ + h;

    float wb[3][12];
#pragma unroll
    for (int p = 0; p < 2; p++) {
#pragma unroll
        for (int q = 0; q < 4; q++) {
            wb[p][q]     = pA[(p * 4 + q) * H_];
            wb[p][4 + q] = pC[(p * 4 + q) * H_];
            wb[p][8 + q] = pS[(p * 4 + q) * H_];
        }
    }

#pragma unroll
    for (int cc = 0; cc < 16; cc++) {
        const int cur = cc % 3;
        if (cc < 14) {
            const int nb  = (cc + 2) % 3;
            const int off = (cc + 2) * 4;
#pragma unroll
            for (int q = 0; q < 4; q++) {
                wb[nb][q]     = pA[(off + q) * H_];
                wb[nb][4 + q] = pC[(off + q) * H_];
                wb[nb][8 + q] = pS[(off + q) * H_];
            }
        }
        const ull wa01 = pack2(wb[cur][0], wb[cur][1]);
        const ull wa23 = pack2(wb[cur][2], wb[cur][3]);
        const ull wc01 = pack2(wb[cur][4], wb[cur][5]);
        const ull wc23 = pack2(wb[cur][6], wb[cur][7]);
        const ull ws01 = pack2(wb[cur][8], wb[cur][9]);
        const ull ws23 = pack2(wb[cur][10], wb[cur][11]);
        const int d0 = dBase + cc * 4;
#pragma unroll
        for (int r = 0; r < RW; r++) {
            const ulonglong2 xv = *(const ulonglong2*)&xs[r][d0];
            fma2(accA[r], xv.x, wa01); fma2(accA[r], xv.y, wa23);
            fma2(accC[r], xv.x, wc01); fma2(accC[r], xv.y, wc23);
            fma2(accS[r], xv.x, ws01); fma2(accS[r], xv.y, ws23);
        }
    }

    if (half == 1) {
#pragma unroll
        for (int r = 0; r < RW; r++) {
            redA[r][h] = hadd2(accA[r]);
            redC[r][h] = hadd2(accC[r]);
            redS[r][h] = hadd2(accS[r]);
        }
    }
    __syncthreads();

    if (half == 0) {
        const float bc  = b1c[h];
        const float bs  = b1s[h];
        const float w2s = W2s[h];
        const float w2c = W2c[h];
#pragma unroll
        for (int r = 0; r < RW; r++) {
            const float a = hadd2(accA[r]) + redA[r][h];
            const float c = hadd2(accC[r]) + redC[r][h] + bc;
            gA[(size_t)(rowBase + r) * H_ + h] = a;
            gC[(size_t)(rowBase + r) * H_ + h] = c;
            float t  = fmaxf(hadd2(accS[r]) + redS[r][h] + bs, 0.f) * w2s;
            float ta = a * w2c;
            float tc = c * w2c;
#pragma unroll
            for (int off = 16; off > 0; off >>= 1) {
                t  += __shfl_down_sync(0xffffffffu, t,  off);
                ta += __shfl_down_sync(0xffffffffu, ta, off);
                tc += __shfl_down_sync(0xffffffffu, tc, off);
            }
            if ((h & 31) == 0) {
                red4d[h >> 5][r] = t;
                red4a[h >> 5][r] = ta;
                red4c[h >> 5][r] = tc;
            }
        }
    }
    __syncthreads();
    if (tid < RW) {
        const float sd = red4d[0][tid] + red4d[1][tid] + red4d[2][tid] + red4d[3][tid] + b2s[0];
        gDiag[rowBase + tid] = 1.f / (1.f + __expf(-sd));
        gWA[rowBase + tid] = red4a[0][tid] + red4a[1][tid] + red4a[2][tid] + red4a[3][tid];
        gWC[rowBase + tid] = red4c[0][tid] + red4c[1][tid] + red4c[2][tid] + red4c[3][tid];
    }
}

// ---------------------------------------------------------------------------
// Pair kernel v12: 64x64 tile, 512 thr, 4x2 micro (broadcast A rows).
// Inner loop uses relu(x)w = 0.5(xw + |x|w): accumulate w*|a+c| only
// (add2 + 64-bit AND + fma2, NO pack/unpack movs); linear part comes from
// precomputed gWA + gWC.
// ---------------------------------------------------------------------------
#define PSTRIDE 132
#define SMEM_PAIR_BYTES ((2 * 64 * PSTRIDE + 128 + 64 + 64 + 16) * 4)

__global__ __launch_bounds__(512) void pair_kernel(
    const float* __restrict__ W2c, const float* __restrict__ b2c,
    float* __restrict__ out)
{
    extern __shared__ float sm[];
    float* As = sm;                             // [64][132]
    float* Cs = sm + 64 * PSTRIDE;              // [64][132]
    float* ws = sm + 2 * 64 * PSTRIDE;          // [128]
    float* wa = ws + 128;                       // [64]
    float* wc = wa + 64;                        // [64]

    int t = blockIdx.x, ti = 0;
    while (t >= 8 - ti) { t -= 8 - ti; ti++; }
    const int tj = ti + t;
    const int b  = blockIdx.y;

    const int tid = threadIdx.x;
    const int i0 = ti * 64, j0 = tj * 64;

    {
        const float4* ga4 = (const float4*)(gA + ((size_t)b * N_ + i0) * H_);
        const float4* gc4 = (const float4*)(gC + ((size_t)b * N_ + j0) * H_);
#pragma unroll
        for (int k = 0; k < 4; k++) {
            const int e = k * 512 + tid;
            const int r = e >> 5, c = e & 31;
            ((float4*)&As[r * PSTRIDE])[c] = ga4[r * 32 + c];
            ((float4*)&Cs[r * PSTRIDE])[c] = gc4[r * 32 + c];
        }
        if (tid < 128)      ws[tid] = W2c[tid];
        else if (tid < 192) wa[tid - 128] = gWA[b * N_ + i0 + (tid - 128)];
        else if (tid < 256) wc[tid - 192] = gWC[b * N_ + j0 + (tid - 192)];
    }
    __syncthreads();

    const int ty = tid >> 5;     // warp id -> rows ty+16k (broadcast loads)
    const int tx = tid & 31;     // lane    -> cols tx+32m (conflict-free)

    const float* aBase = &As[ty * PSTRIDE];
    const float* cBase = &Cs[tx * PSTRIDE];

    ull acc[4][2];
#pragma unroll
    for (int k = 0; k < 4; k++) { acc[k][0] = 0ull; acc[k][1] = 0ull; }

#pragma unroll 4
    for (int hh = 0; hh < H_; hh += 4) {
        ulonglong2 av[4], cv[2];
#pragma unroll
        for (int k = 0; k < 4; k++)
            av[k] = *(const ulonglong2*)(aBase + (16 * k) * PSTRIDE + hh);
#pragma unroll
        for (int m = 0; m < 2; m++)
            cv[m] = *(const ulonglong2*)(cBase + (32 * m) * PSTRIDE + hh);
        const ulonglong2 wv = *(const ulonglong2*)&ws[hh];

#pragma unroll
        for (int k = 0; k < 4; k++) {
#pragma unroll
            for (int m = 0; m < 2; m++) {
                const ull x0 = add2(av[k].x, cv[m].x) & ABSMASK2;
                const ull x1 = add2(av[k].y, cv[m].y) & ABSMASK2;
                fma2(acc[k][m], x0, wv.x);
                fma2(acc[k][m], x1, wv.y);
            }
        }
    }

    const float bb = b2c[0];
    float sv[4][2];
#pragma unroll
    for (int k = 0; k < 4; k++) {
        const float wai = wa[ty + 16 * k];           // warp-broadcast
#pragma unroll
        for (int m = 0; m < 2; m++) {
            const float base = 0.5f * (wai + wc[tx + 32 * m]) + bb;
            const float pre  = fmaf(0.5f, hadd2(acc[k][m]), base);
            sv[k][m] = 1.f / (1.f + __expf(-pre));
        }
    }

    __syncthreads();
    float* St = As;
#define ST(i, j) St[(i) * 65 + (j)]

    if (ti != tj) {
#pragma unroll
        for (int k = 0; k < 4; k++)
#pragma unroll
            for (int m = 0; m < 2; m++)
                ST(ty + 16 * k, tx + 32 * m) = sv[k][m];
        __syncthreads();

        for (int q = tid; q < 1024; q += 512) {
            const int r = q >> 4, c = (q & 15) * 4;
            float4 v = make_float4(ST(r, c), ST(r, c + 1), ST(r, c + 2), ST(r, c + 3));
            *(float4*)&out[((size_t)b * N_ + i0 + r) * N_ + j0 + c] = v;
        }
        for (int q = tid; q < 1024; q += 512) {
            const int r = q >> 4, c = (q & 15) * 4;
            float4 v = make_float4(ST(c, r), ST(c + 1, r), ST(c + 2, r), ST(c + 3, r));
            *(float4*)&out[((size_t)b * N_ + j0 + r) * N_ + i0 + c] = v;
        }
    } else {
        const int gi0 = b * N_ + i0;
#pragma unroll
        for (int k = 0; k < 4; k++) {
#pragma unroll
            for (int m = 0; m < 2; m++) {
                const int i = ty + 16 * k, j = tx + 32 * m;
                if (i < j)       { ST(i, j) = sv[k][m]; ST(j, i) = sv[k][m]; }
                else if (i == j) { ST(i, i) = gDiag[gi0 + i]; }
            }
        }
        __syncthreads();
        for (int q = tid; q < 1024; q += 512) {
            const int r = q >> 4, c = (q & 15) * 4;
            float4 v = make_float4(ST(r, c), ST(r, c + 1), ST(r, c + 2), ST(r, c + 3));
            *(float4*)&out[((size_t)b * N_ + i0 + r) * N_ + j0 + c] = v;
        }
    }
#undef ST
}

// ---------------------------------------------------------------------------
extern "C" void kernel_launch(void* const* d_in, const int* in_sizes, int n_in,
                              void* d_out, int out_size)
{
    const float* X   = (const float*)d_in[0];
    const float* W1c = (const float*)d_in[1];
    const float* b1c = (const float*)d_in[2];
    const float* W2c = (const float*)d_in[3];
    const float* b2c = (const float*)d_in[4];
    const float* W1s = (const float*)d_in[5];
    const float* b1s = (const float*)d_in[6];
    const float* W2s = (const float*)d_in[7];
    const float* b2s = (const float*)d_in[8];
    float* out = (float*)d_out;

    static bool attrSet = false;
    if (!attrSet) {
        cudaFuncSetAttribute(pair_kernel,
                             cudaFuncAttributeMaxDynamicSharedMemorySize,
                             SMEM_PAIR_BYTES);
        attrSet = true;
    }

    precompute_kernel<<<(B_ * N_) / RW, 256>>>(X, W1c, b1c, W1s, b1s, W2s, b2s, W2c);

    dim3 grid(36, B_);   // triangular 64x64 tiles x batch
    pair_kernel<<<grid, 512, SMEM_PAIR_BYTES>>>(W2c, b2c, out);
}